// round 1
// baseline (speedup 1.0000x reference)
#include <cuda_runtime.h>
#include <math.h>

// Problem constants (fixed shapes per reference)
#define BATCH   2
#define SLEN    2048
#define DIN     2048
#define DOUT    2048
#define NHEADS  16
#define DH      128          // head dim
#define ROWS    (BATCH*SLEN) // 4096
#define QKVCOLS (3*DOUT)     // 6144

// Scratch (allocation-free rule: __device__ globals)
__device__ float g_qkv[(size_t)ROWS * QKVCOLS];   // [4096, 6144]
__device__ float g_attn[(size_t)ROWS * DOUT];     // [4096, 2048]

// ---------------------------------------------------------------------------
// SGEMM: C[M,N] = A[M,K] @ B[K,N] (+bias). BM=BN=128, BK=8, TM=TN=8, 256 thr.
// M,N,K all multiples of tile sizes here (no bounds checks needed).
// ---------------------------------------------------------------------------
template <bool BIAS>
__device__ __forceinline__ void sgemm_dev(const float* __restrict__ A,
                                          const float* __restrict__ B,
                                          const float* __restrict__ bias,
                                          float* __restrict__ C,
                                          int N, int K) {
    const int BM = 128, BN = 128, BK = 8, TM = 8, TN = 8;
    __shared__ float As[BK][BM];
    __shared__ float Bs[BK][BN];

    int t  = threadIdx.x;           // 0..255
    int bm = blockIdx.y, bn = blockIdx.x;

    const float* Ab = A + (size_t)bm * BM * K;
    const float* Bb = B + (size_t)bn * BN;

    float acc[TM][TN];
#pragma unroll
    for (int i = 0; i < TM; i++)
#pragma unroll
        for (int j = 0; j < TN; j++) acc[i][j] = 0.f;

    int arow = t >> 1, acol = (t & 1) * 4;   // A: 128 rows x 8 cols per step
    int brow = t >> 5, bcol = (t & 31) * 4;  // B: 8 rows x 128 cols per step
    int tx = t & 15, ty = t >> 4;

    for (int k0 = 0; k0 < K; k0 += BK) {
        float4 av = *reinterpret_cast<const float4*>(Ab + (size_t)arow * K + k0 + acol);
        float4 bv = *reinterpret_cast<const float4*>(Bb + (size_t)(k0 + brow) * N + bcol);
        __syncthreads();  // protect smem from previous iteration's readers
        As[acol + 0][arow] = av.x;
        As[acol + 1][arow] = av.y;
        As[acol + 2][arow] = av.z;
        As[acol + 3][arow] = av.w;
        *reinterpret_cast<float4*>(&Bs[brow][bcol]) = bv;
        __syncthreads();

#pragma unroll
        for (int k = 0; k < BK; k++) {
            float ar[TM], br[TN];
#pragma unroll
            for (int i = 0; i < TM; i++) ar[i] = As[k][ty * TM + i];
#pragma unroll
            for (int j = 0; j < TN; j++) br[j] = Bs[k][tx * TN + j];
#pragma unroll
            for (int i = 0; i < TM; i++)
#pragma unroll
                for (int j = 0; j < TN; j++) acc[i][j] = fmaf(ar[i], br[j], acc[i][j]);
        }
    }

#pragma unroll
    for (int i = 0; i < TM; i++) {
        int row = bm * BM + ty * TM + i;
#pragma unroll
        for (int j = 0; j < TN; j += 4) {
            int col = bn * BN + tx * TN + j;
            float4 v;
            v.x = acc[i][j + 0];
            v.y = acc[i][j + 1];
            v.z = acc[i][j + 2];
            v.w = acc[i][j + 3];
            if (BIAS) {
                v.x += bias[col + 0];
                v.y += bias[col + 1];
                v.z += bias[col + 2];
                v.w += bias[col + 3];
            }
            *reinterpret_cast<float4*>(C + (size_t)row * N + col) = v;
        }
    }
}

__global__ __launch_bounds__(256) void k_gemm_qkv(const float* __restrict__ x,
                                                  const float* __restrict__ Wqkv) {
    sgemm_dev<false>(x, Wqkv, nullptr, g_qkv, QKVCOLS, DIN);
}

__global__ __launch_bounds__(256) void k_gemm_proj(const float* __restrict__ Wproj,
                                                   const float* __restrict__ bproj,
                                                   float* __restrict__ out) {
    sgemm_dev<true>(g_attn, Wproj, bproj, out, DOUT, DOUT);
}

// ---------------------------------------------------------------------------
// Flash attention (fp32, causal). One query row per warp, 8 warps/block.
// Key/Value tiles of 32. K stored transposed+padded for conflict-free LDS.
// qkv layout: row = b*SLEN + s, col = part*2048 + h*128 + d (part: 0=q,1=k,2=v)
// ---------------------------------------------------------------------------
__global__ __launch_bounds__(256) void k_attn() {
    int qblk = blockIdx.x;   // 0..255 (8 queries each)
    int h    = blockIdx.y;   // 0..15
    int b    = blockIdx.z;   // 0..1
    int warp = threadIdx.x >> 5;
    int lane = threadIdx.x & 31;
    int qi   = qblk * 8 + warp;   // this warp's query index

    __shared__ float sQ[8][DH];        // 4 KB
    __shared__ float sKt[DH][33];      // transposed K tile, padded (16.9 KB)
    __shared__ float sV[32][DH];       // 16 KB

    const size_t rowstride = QKVCOLS;
    const float* qbase = g_qkv + (size_t)(b * SLEN) * rowstride + 0    + h * DH;
    const float* kbase = g_qkv + (size_t)(b * SLEN) * rowstride + 2048 + h * DH;
    const float* vbase = g_qkv + (size_t)(b * SLEN) * rowstride + 4096 + h * DH;

    // Load the 8 query rows for this block
    for (int i = threadIdx.x; i < 8 * DH; i += 256) {
        int r = i / DH, d = i % DH;
        sQ[r][d] = qbase[(size_t)(qblk * 8 + r) * rowstride + d];
    }

    float o0 = 0.f, o1 = 0.f, o2 = 0.f, o3 = 0.f;
    float m = -1e30f, l = 0.f;
    const float scale = 0.08838834764831845f;  // 1/sqrt(128)

    int kmax   = qblk * 8 + 7;       // block's max query index (causal bound)
    int ntiles = kmax / 32 + 1;

    for (int tile = 0; tile < ntiles; ++tile) {
        int k0 = tile * 32;
        __syncthreads();  // previous tile's consumers done (also covers sQ load)
        // Load 32 keys (transposed) and values
        for (int i = threadIdx.x; i < 32 * DH; i += 256) {
            int kk = i / DH, d = i % DH;
            sKt[d][kk] = kbase[(size_t)(k0 + kk) * rowstride + d];
            sV[kk][d]  = vbase[(size_t)(k0 + kk) * rowstride + d];
        }
        __syncthreads();

        // Score for key (k0+lane) vs query qi
        float s = 0.f;
#pragma unroll 8
        for (int d = 0; d < DH; ++d)
            s = fmaf(sQ[warp][d], sKt[d][lane], s);
        s *= scale;
        if (k0 + lane > qi) s = -1e30f;

        // Online softmax update
        float smax = s;
#pragma unroll
        for (int off = 16; off > 0; off >>= 1)
            smax = fmaxf(smax, __shfl_xor_sync(0xffffffffu, smax, off));
        float mnew  = fmaxf(m, smax);
        float p     = __expf(s - mnew);
        float alpha = __expf(m - mnew);
        m = mnew;

        float psum = p;
#pragma unroll
        for (int off = 16; off > 0; off >>= 1)
            psum += __shfl_xor_sync(0xffffffffu, psum, off);
        l = l * alpha + psum;

        o0 *= alpha; o1 *= alpha; o2 *= alpha; o3 *= alpha;
#pragma unroll 4
        for (int j = 0; j < 32; ++j) {
            float pj = __shfl_sync(0xffffffffu, p, j);
            o0 = fmaf(pj, sV[j][lane +  0], o0);
            o1 = fmaf(pj, sV[j][lane + 32], o1);
            o2 = fmaf(pj, sV[j][lane + 64], o2);
            o3 = fmaf(pj, sV[j][lane + 96], o3);
        }
    }

    float inv = 1.f / l;
    float* obase = g_attn + (size_t)(b * SLEN + qi) * DOUT + h * DH;
    obase[lane +  0] = o0 * inv;
    obase[lane + 32] = o1 * inv;
    obase[lane + 64] = o2 * inv;
    obase[lane + 96] = o3 * inv;
}

// ---------------------------------------------------------------------------
// Launch: x -> qkv -> attention -> projection (+bias) -> d_out
// ---------------------------------------------------------------------------
extern "C" void kernel_launch(void* const* d_in, const int* in_sizes, int n_in,
                              void* d_out, int out_size) {
    const float* x     = (const float*)d_in[0];
    const float* Wqkv  = (const float*)d_in[1];
    const float* Wproj = (const float*)d_in[2];
    const float* bproj = (const float*)d_in[3];
    float* out = (float*)d_out;

    (void)in_sizes; (void)n_in; (void)out_size;

    // GEMM1: [4096,2048] @ [2048,6144] -> g_qkv
    k_gemm_qkv<<<dim3(QKVCOLS / 128, ROWS / 128), 256>>>(x, Wqkv);

    // Attention: g_qkv -> g_attn
    k_attn<<<dim3(SLEN / 8, NHEADS, BATCH), 256>>>();

    // GEMM2: [4096,2048] @ [2048,2048] + bias -> out
    k_gemm_proj<<<dim3(DOUT / 128, ROWS / 128), 256>>>(Wproj, bproj, out);
}

// round 3
// speedup vs baseline: 1.5354x; 1.5354x over previous
#include <cuda_runtime.h>
#include <cuda_bf16.h>
#include <cstdint>
#include <math.h>

// Problem constants
#define BATCH   2
#define SLEN    2048
#define DIN     2048
#define DOUT    2048
#define NHEADS  16
#define DH      128
#define ROWS    (BATCH*SLEN)   // 4096
#define QKVCOLS (3*DOUT)       // 6144
#define KP      6144           // packed K' = 3*2048 (bf16x3 terms folded into K)

// ---------------------------------------------------------------------------
// Scratch (__device__ globals; allocation-free rule)
// ---------------------------------------------------------------------------
__device__ float         g_qkv[(size_t)ROWS * QKVCOLS];   // fp32 QKV (100MB)
__device__ __nv_bfloat16 g_x3[(size_t)ROWS * KP];         // x packed [Ah|Ah|Al]
__device__ __nv_bfloat16 g_wqkv3[(size_t)QKVCOLS * KP];   // Wqkv^T packed [Bh|Bl|Bh]
__device__ __nv_bfloat16 g_wp3[(size_t)DOUT * KP];        // Wproj^T packed [Bh|Bl|Bh]
__device__ __nv_bfloat16 g_a3[(size_t)ROWS * KP];         // attn out packed [Ah|Ah|Al]

// ---------------------------------------------------------------------------
// Helpers
// ---------------------------------------------------------------------------
__device__ __forceinline__ uint32_t smem_to_u32(const void* p) {
    uint32_t a;
    asm("{ .reg .u64 t; cvta.to.shared.u64 t, %1; cvt.u32.u64 %0, t; }" : "=r"(a) : "l"(p));
    return a;
}

__device__ __forceinline__ void split_bf16(float a, __nv_bfloat16& h, __nv_bfloat16& l) {
    h = __float2bfloat16(a);
    l = __float2bfloat16(a - __bfloat162float(h));
}

__device__ __forceinline__ void ldsm4(uint32_t& r0, uint32_t& r1, uint32_t& r2, uint32_t& r3,
                                      uint32_t addr) {
    asm volatile("ldmatrix.sync.aligned.m8n8.x4.shared.b16 {%0,%1,%2,%3}, [%4];"
                 : "=r"(r0), "=r"(r1), "=r"(r2), "=r"(r3) : "r"(addr));
}

__device__ __forceinline__ void mma16816(float* c,
                                         uint32_t a0, uint32_t a1, uint32_t a2, uint32_t a3,
                                         uint32_t b0, uint32_t b1) {
    asm volatile("mma.sync.aligned.m16n8k16.row.col.f32.bf16.bf16.f32 "
                 "{%0,%1,%2,%3}, {%4,%5,%6,%7}, {%8,%9}, {%0,%1,%2,%3};"
                 : "+f"(c[0]), "+f"(c[1]), "+f"(c[2]), "+f"(c[3])
                 : "r"(a0), "r"(a1), "r"(a2), "r"(a3), "r"(b0), "r"(b1));
}

// ---------------------------------------------------------------------------
// Pack/split kernels
// ---------------------------------------------------------------------------
// x [4096,2048] fp32 -> g_x3 [4096,6144] bf16: hi@k, hi@2048+k, lo@4096+k
__global__ __launch_bounds__(256) void k_split_pack(const float* __restrict__ in,
                                                    __nv_bfloat16* __restrict__ out) {
    size_t i = (size_t)blockIdx.x * blockDim.x + threadIdx.x;  // over ROWS*2048/4
    int r  = (int)(i >> 9);          // / (2048/4)
    int kq = (int)(i & 511);
    float4 v = reinterpret_cast<const float4*>(in)[i];
    __nv_bfloat16 h0,h1,h2,h3,l0,l1,l2,l3;
    split_bf16(v.x,h0,l0); split_bf16(v.y,h1,l1);
    split_bf16(v.z,h2,l2); split_bf16(v.w,h3,l3);
    __nv_bfloat162 H0 = __halves2bfloat162(h0,h1), H1 = __halves2bfloat162(h2,h3);
    __nv_bfloat162 L0 = __halves2bfloat162(l0,l1), L1 = __halves2bfloat162(l2,l3);
    __nv_bfloat162* o = reinterpret_cast<__nv_bfloat162*>(out + (size_t)r * KP) + kq*2;
    o[0] = H0; o[1] = H1;                  // seg0: hi
    o[1024] = H0; o[1025] = H1;            // seg1 (+2048 elems = +1024 bf162): hi
    o[2048] = L0; o[2049] = L1;            // seg2 (+4096): lo
}

// W [2048, C] fp32 -> out [C, 6144] bf16 (transpose): hi@k, lo@2048+k, hi@4096+k
__global__ __launch_bounds__(256) void k_tsplit_pack(const float* __restrict__ in,
                                                     __nv_bfloat16* __restrict__ out,
                                                     int C) {
    __shared__ float t[32][33];
    int c0 = blockIdx.x * 32, r0 = blockIdx.y * 32;
    int tx = threadIdx.x, ty = threadIdx.y;   // 32 x 8
#pragma unroll
    for (int i = 0; i < 32; i += 8)
        t[ty + i][tx] = in[(size_t)(r0 + ty + i) * C + c0 + tx];
    __syncthreads();
#pragma unroll
    for (int i = 0; i < 32; i += 8) {
        float a = t[tx][ty + i];            // = in[r0+tx][c0+ty+i]
        __nv_bfloat16 h, l;
        split_bf16(a, h, l);
        size_t n = (size_t)(c0 + ty + i);
        int    k = r0 + tx;
        out[n * KP + k]        = h;
        out[n * KP + 2048 + k] = l;
        out[n * KP + 4096 + k] = h;
    }
}

// ---------------------------------------------------------------------------
// bf16 GEMM via mma.sync: C[m,n] = sum_k A[m,k]*B[n,k], A[M,KP], B[N,KP].
// CTA 128x128, BK=64, double-buffered cp.async, 8 warps x (64x32) tiles.
// ---------------------------------------------------------------------------
#define BKG   64
#define NKIT  (KP / BKG)        // 96
#define TILE_BYTES 16384        // 128 rows x 128B
#define GEMM_SMEM  (1024 + 4 * TILE_BYTES)

__device__ __forceinline__ void load_tile_pair(uint32_t sA, uint32_t sB,
                                               const __nv_bfloat16* gA,
                                               const __nv_bfloat16* gB, int tid) {
#pragma unroll
    for (int t = 0; t < 4; ++t) {
        int i = tid + t * 256;                  // 0..1023
        int row = i >> 3, c = i & 7;
        uint32_t sw = (uint32_t)row * 128 + ((c * 16) ^ ((row & 7) * 16));
        const void* ga = gA + (size_t)row * KP + c * 8;
        const void* gb = gB + (size_t)row * KP + c * 8;
        asm volatile("cp.async.cg.shared.global [%0], [%1], 16;" :: "r"(sA + sw), "l"(ga));
        asm volatile("cp.async.cg.shared.global [%0], [%1], 16;" :: "r"(sB + sw), "l"(gb));
    }
}

template <bool BIAS>
__global__ __launch_bounds__(256) void k_gemm_mma(const __nv_bfloat16* __restrict__ A,
                                                  const __nv_bfloat16* __restrict__ B,
                                                  const float* __restrict__ bias,
                                                  float* __restrict__ C, int N) {
    extern __shared__ char smraw[];
    uint32_t sbase = (smem_to_u32(smraw) + 1023) & ~1023u;
    const int tid = threadIdx.x;
    const int m0 = blockIdx.y * 128, n0 = blockIdx.x * 128;
    const __nv_bfloat16* Ab = A + (size_t)m0 * KP;
    const __nv_bfloat16* Bb = B + (size_t)n0 * KP;

    // Prefetch tile 0 into buffer 0
    load_tile_pair(sbase, sbase + TILE_BYTES, Ab, Bb, tid);
    asm volatile("cp.async.commit_group;" ::: "memory");

    float c[4][4][4];
#pragma unroll
    for (int i = 0; i < 4; i++)
#pragma unroll
        for (int j = 0; j < 4; j++)
#pragma unroll
            for (int q = 0; q < 4; q++) c[i][j][q] = 0.f;

    const int wid = tid >> 5, lane = tid & 31;
    const int wm = wid & 1, wn = wid >> 1;             // 2 x 4 warp grid
    const int a_row_base = wm * 64 + ((lane >> 3) & 1) * 8 + (lane & 7);
    const int a_byte     = (lane >> 4) * 16;
    const int b_row_off  = ((lane >> 4) & 1) * 8 + (lane & 7);
    const int b_byte     = ((lane >> 3) & 1) * 16;

    for (int kt = 0; kt < NKIT; ++kt) {
        uint32_t bufA = sbase + (kt & 1) * (2 * TILE_BYTES);
        uint32_t bufB = bufA + TILE_BYTES;
        if (kt + 1 < NKIT) {
            uint32_t nA = sbase + ((kt + 1) & 1) * (2 * TILE_BYTES);
            load_tile_pair(nA, nA + TILE_BYTES, Ab + (kt + 1) * BKG, Bb + (kt + 1) * BKG, tid);
        }
        asm volatile("cp.async.commit_group;" ::: "memory");
        asm volatile("cp.async.wait_group 1;" ::: "memory");
        __syncthreads();

#pragma unroll
        for (int s = 0; s < 4; ++s) {          // 4 k16-steps per BK=64
            uint32_t a[4][4], b[2][4];
#pragma unroll
            for (int am = 0; am < 4; ++am) {
                int row = a_row_base + am * 16;
                uint32_t off = (uint32_t)row * 128 + ((s * 32 + a_byte) ^ ((row & 7) * 16));
                ldsm4(a[am][0], a[am][1], a[am][2], a[am][3], bufA + off);
            }
#pragma unroll
            for (int p = 0; p < 2; ++p) {
                int row = wn * 32 + p * 16 + b_row_off;
                uint32_t off = (uint32_t)row * 128 + ((s * 32 + b_byte) ^ ((row & 7) * 16));
                ldsm4(b[p][0], b[p][1], b[p][2], b[p][3], bufB + off);
            }
#pragma unroll
            for (int am = 0; am < 4; ++am)
#pragma unroll
                for (int an = 0; an < 4; ++an)
                    mma16816(c[am][an], a[am][0], a[am][1], a[am][2], a[am][3],
                             b[an >> 1][(an & 1) * 2], b[an >> 1][(an & 1) * 2 + 1]);
        }
        __syncthreads();
    }

    // Epilogue
    const int mrow = m0 + wm * 64;
    const int ncol = n0 + wn * 32;
#pragma unroll
    for (int am = 0; am < 4; ++am) {
        int r = mrow + am * 16 + (lane >> 2);
#pragma unroll
        for (int an = 0; an < 4; ++an) {
            int col = ncol + an * 8 + (lane & 3) * 2;
            float2 v0 = make_float2(c[am][an][0], c[am][an][1]);
            float2 v1 = make_float2(c[am][an][2], c[am][an][3]);
            if (BIAS) {
                float b0 = bias[col], b1 = bias[col + 1];
                v0.x += b0; v0.y += b1; v1.x += b0; v1.y += b1;
            }
            *reinterpret_cast<float2*>(C + (size_t)r * N + col)       = v0;
            *reinterpret_cast<float2*>(C + (size_t)(r + 8) * N + col) = v1;
        }
    }
}

// ---------------------------------------------------------------------------
// Flash attention (fp32, causal). Unchanged math; emits packed bf16x3 output.
// ---------------------------------------------------------------------------
__global__ __launch_bounds__(256) void k_attn() {
    int qblk = blockIdx.x;
    int h    = blockIdx.y;
    int b    = blockIdx.z;
    int warp = threadIdx.x >> 5;
    int lane = threadIdx.x & 31;
    int qi   = qblk * 8 + warp;

    __shared__ float sQ[8][DH];
    __shared__ float sKt[DH][33];
    __shared__ float sV[32][DH];

    const size_t rowstride = QKVCOLS;
    const float* qbase = g_qkv + (size_t)(b * SLEN) * rowstride + 0    + h * DH;
    const float* kbase = g_qkv + (size_t)(b * SLEN) * rowstride + 2048 + h * DH;
    const float* vbase = g_qkv + (size_t)(b * SLEN) * rowstride + 4096 + h * DH;

    for (int i = threadIdx.x; i < 8 * DH; i += 256) {
        int r = i / DH, d = i % DH;
        sQ[r][d] = qbase[(size_t)(qblk * 8 + r) * rowstride + d];
    }

    float o0 = 0.f, o1 = 0.f, o2 = 0.f, o3 = 0.f;
    float m = -1e30f, l = 0.f;
    const float scale = 0.08838834764831845f;

    int kmax   = qblk * 8 + 7;
    int ntiles = kmax / 32 + 1;

    for (int tile = 0; tile < ntiles; ++tile) {
        int k0 = tile * 32;
        __syncthreads();
        for (int i = threadIdx.x; i < 32 * DH; i += 256) {
            int kk = i / DH, d = i % DH;
            sKt[d][kk] = kbase[(size_t)(k0 + kk) * rowstride + d];
            sV[kk][d]  = vbase[(size_t)(k0 + kk) * rowstride + d];
        }
        __syncthreads();

        float s = 0.f;
#pragma unroll 8
        for (int d = 0; d < DH; ++d)
            s = fmaf(sQ[warp][d], sKt[d][lane], s);
        s *= scale;
        if (k0 + lane > qi) s = -1e30f;

        float smax = s;
#pragma unroll
        for (int off = 16; off > 0; off >>= 1)
            smax = fmaxf(smax, __shfl_xor_sync(0xffffffffu, smax, off));
        float mnew  = fmaxf(m, smax);
        float p     = __expf(s - mnew);
        float alpha = __expf(m - mnew);
        m = mnew;

        float psum = p;
#pragma unroll
        for (int off = 16; off > 0; off >>= 1)
            psum += __shfl_xor_sync(0xffffffffu, psum, off);
        l = l * alpha + psum;

        o0 *= alpha; o1 *= alpha; o2 *= alpha; o3 *= alpha;
#pragma unroll 4
        for (int j = 0; j < 32; ++j) {
            float pj = __shfl_sync(0xffffffffu, p, j);
            o0 = fmaf(pj, sV[j][lane +  0], o0);
            o1 = fmaf(pj, sV[j][lane + 32], o1);
            o2 = fmaf(pj, sV[j][lane + 64], o2);
            o3 = fmaf(pj, sV[j][lane + 96], o3);
        }
    }

    float inv = 1.f / l;
    size_t rowb = (size_t)(b * SLEN + qi) * KP + h * DH;   // packed A' row
    float v[4] = {o0 * inv, o1 * inv, o2 * inv, o3 * inv};
#pragma unroll
    for (int q = 0; q < 4; ++q) {
        __nv_bfloat16 hh, ll;
        split_bf16(v[q], hh, ll);
        size_t o = rowb + lane + q * 32;
        g_a3[o]        = hh;    // seg0: hi
        g_a3[o + 2048] = hh;    // seg1: hi
        g_a3[o + 4096] = ll;    // seg2: lo
    }
}

// ---------------------------------------------------------------------------
// Launch
// ---------------------------------------------------------------------------
extern "C" void kernel_launch(void* const* d_in, const int* in_sizes, int n_in,
                              void* d_out, int out_size) {
    const float* x     = (const float*)d_in[0];
    const float* Wqkv  = (const float*)d_in[1];
    const float* Wproj = (const float*)d_in[2];
    const float* bproj = (const float*)d_in[3];
    float* out = (float*)d_out;
    (void)in_sizes; (void)n_in; (void)out_size;

    cudaFuncSetAttribute(k_gemm_mma<false>, cudaFuncAttributeMaxDynamicSharedMemorySize, GEMM_SMEM);
    cudaFuncSetAttribute(k_gemm_mma<true>,  cudaFuncAttributeMaxDynamicSharedMemorySize, GEMM_SMEM);

    __nv_bfloat16 *x3, *wq3, *wp3, *a3;
    float* qkv;
    cudaGetSymbolAddress((void**)&x3,  g_x3);
    cudaGetSymbolAddress((void**)&wq3, g_wqkv3);
    cudaGetSymbolAddress((void**)&wp3, g_wp3);
    cudaGetSymbolAddress((void**)&a3,  g_a3);
    cudaGetSymbolAddress((void**)&qkv, g_qkv);

    // 1) Pack x -> [Ah|Ah|Al]
    k_split_pack<<<(ROWS * 2048 / 4) / 256, 256>>>(x, x3);
    // 2) Transpose+pack Wqkv [2048,6144] -> [6144, 6144] ([Bh|Bl|Bh])
    k_tsplit_pack<<<dim3(QKVCOLS / 32, 2048 / 32), dim3(32, 8)>>>(Wqkv, wq3, QKVCOLS);
    // 3) Transpose+pack Wproj [2048,2048] -> [2048, 6144]
    k_tsplit_pack<<<dim3(DOUT / 32, 2048 / 32), dim3(32, 8)>>>(Wproj, wp3, DOUT);

    // 4) GEMM1: qkv = x @ Wqkv  (fp32 out) [4096,6144]
    k_gemm_mma<false><<<dim3(QKVCOLS / 128, ROWS / 128), 256, GEMM_SMEM>>>(
        x3, wq3, nullptr, qkv, QKVCOLS);

    // 5) Attention -> g_a3 (packed bf16x3)
    k_attn<<<dim3(SLEN / 8, NHEADS, BATCH), 256>>>();

    // 6) GEMM2: out = attn @ Wproj + bias  [4096,2048]
    k_gemm_mma<true><<<dim3(DOUT / 128, ROWS / 128), 256, GEMM_SMEM>>>(
        a3, wp3, bproj, out, DOUT);
}

// round 5
// speedup vs baseline: 4.6761x; 3.0455x over previous
#include <cuda_runtime.h>
#include <cuda_bf16.h>
#include <cstdint>
#include <math.h>

// Problem constants
#define BATCH   2
#define SLEN    2048
#define DIN     2048
#define DOUT    2048
#define NHEADS  16
#define DH      128
#define ROWS    (BATCH*SLEN)   // 4096
#define QKVCOLS (3*DOUT)       // 6144
#define KP      6144           // packed K' = 3*2048
#define NBH     (BATCH*NHEADS) // 32
#define HEADELEMS ((size_t)SLEN*DH)  // 262144 per (b,h)

// ---------------------------------------------------------------------------
// Scratch
// ---------------------------------------------------------------------------
__device__ float         g_qkv[(size_t)ROWS * QKVCOLS];
__device__ __nv_bfloat16 g_x3[(size_t)ROWS * KP];
__device__ __nv_bfloat16 g_wqkv3[(size_t)QKVCOLS * KP];
__device__ __nv_bfloat16 g_wp3[(size_t)DOUT * KP];
__device__ __nv_bfloat16 g_a3[(size_t)ROWS * KP];
// attention operands (per-head layouts, hi/lo splits)
__device__ __nv_bfloat16 g_qh[(size_t)NBH * HEADELEMS];  // [bh][s][d] (pre-scaled)
__device__ __nv_bfloat16 g_ql[(size_t)NBH * HEADELEMS];
__device__ __nv_bfloat16 g_kh[(size_t)NBH * HEADELEMS];  // [bh][s][d]
__device__ __nv_bfloat16 g_kl[(size_t)NBH * HEADELEMS];
__device__ __nv_bfloat16 g_vth[(size_t)NBH * HEADELEMS]; // [bh][d][s]
__device__ __nv_bfloat16 g_vtl[(size_t)NBH * HEADELEMS];

// ---------------------------------------------------------------------------
// Helpers
// ---------------------------------------------------------------------------
__device__ __forceinline__ uint32_t smem_to_u32(const void* p) {
    uint32_t a;
    asm("{ .reg .u64 t; cvta.to.shared.u64 t, %1; cvt.u32.u64 %0, t; }" : "=r"(a) : "l"(p));
    return a;
}
__device__ __forceinline__ void split_bf16(float a, __nv_bfloat16& h, __nv_bfloat16& l) {
    h = __float2bfloat16(a);
    l = __float2bfloat16(a - __bfloat162float(h));
}
__device__ __forceinline__ void split_pack(float a, float b, uint32_t& hi, uint32_t& lo) {
    __nv_bfloat16 ha, la, hb, lb;
    split_bf16(a, ha, la);
    split_bf16(b, hb, lb);
    __nv_bfloat162 vh = __halves2bfloat162(ha, hb);
    __nv_bfloat162 vl = __halves2bfloat162(la, lb);
    hi = *reinterpret_cast<uint32_t*>(&vh);
    lo = *reinterpret_cast<uint32_t*>(&vl);
}
__device__ __forceinline__ void ldsm4(uint32_t& r0, uint32_t& r1, uint32_t& r2, uint32_t& r3,
                                      uint32_t addr) {
    asm volatile("ldmatrix.sync.aligned.m8n8.x4.shared.b16 {%0,%1,%2,%3}, [%4];"
                 : "=r"(r0), "=r"(r1), "=r"(r2), "=r"(r3) : "r"(addr));
}
__device__ __forceinline__ void mma16816(float* c,
                                         uint32_t a0, uint32_t a1, uint32_t a2, uint32_t a3,
                                         uint32_t b0, uint32_t b1) {
    asm volatile("mma.sync.aligned.m16n8k16.row.col.f32.bf16.bf16.f32 "
                 "{%0,%1,%2,%3}, {%4,%5,%6,%7}, {%8,%9}, {%0,%1,%2,%3};"
                 : "+f"(c[0]), "+f"(c[1]), "+f"(c[2]), "+f"(c[3])
                 : "r"(a0), "r"(a1), "r"(a2), "r"(a3), "r"(b0), "r"(b1));
}
__device__ __forceinline__ void cpa16(uint32_t dst, const void* src) {
    asm volatile("cp.async.cg.shared.global [%0], [%1], 16;" :: "r"(dst), "l"(src));
}
#define CP_COMMIT() asm volatile("cp.async.commit_group;" ::: "memory")
#define CP_WAIT1()  asm volatile("cp.async.wait_group 1;" ::: "memory")

// ---------------------------------------------------------------------------
// Pack/split kernels (GEMM inputs)
// ---------------------------------------------------------------------------
__global__ __launch_bounds__(256) void k_split_pack(const float* __restrict__ in,
                                                    __nv_bfloat16* __restrict__ out) {
    size_t i = (size_t)blockIdx.x * blockDim.x + threadIdx.x;
    int r  = (int)(i >> 9);
    int kq = (int)(i & 511);
    float4 v = reinterpret_cast<const float4*>(in)[i];
    __nv_bfloat16 h0,h1,h2,h3,l0,l1,l2,l3;
    split_bf16(v.x,h0,l0); split_bf16(v.y,h1,l1);
    split_bf16(v.z,h2,l2); split_bf16(v.w,h3,l3);
    __nv_bfloat162 H0 = __halves2bfloat162(h0,h1), H1 = __halves2bfloat162(h2,h3);
    __nv_bfloat162 L0 = __halves2bfloat162(l0,l1), L1 = __halves2bfloat162(l2,l3);
    __nv_bfloat162* o = reinterpret_cast<__nv_bfloat162*>(out + (size_t)r * KP) + kq*2;
    o[0] = H0; o[1] = H1;
    o[1024] = H0; o[1025] = H1;
    o[2048] = L0; o[2049] = L1;
}

__global__ __launch_bounds__(256) void k_tsplit_pack(const float* __restrict__ in,
                                                     __nv_bfloat16* __restrict__ out,
                                                     int C) {
    __shared__ float t[32][33];
    int c0 = blockIdx.x * 32, r0 = blockIdx.y * 32;
    int tx = threadIdx.x, ty = threadIdx.y;
#pragma unroll
    for (int i = 0; i < 32; i += 8)
        t[ty + i][tx] = in[(size_t)(r0 + ty + i) * C + c0 + tx];
    __syncthreads();
#pragma unroll
    for (int i = 0; i < 32; i += 8) {
        float a = t[tx][ty + i];
        __nv_bfloat16 h, l;
        split_bf16(a, h, l);
        size_t n = (size_t)(c0 + ty + i);
        int    k = r0 + tx;
        out[n * KP + k]        = h;
        out[n * KP + 2048 + k] = l;
        out[n * KP + 4096 + k] = h;
    }
}

// ---------------------------------------------------------------------------
// Attention pre-passes: g_qkv -> per-head hi/lo bf16 operands
// ---------------------------------------------------------------------------
__global__ __launch_bounds__(256) void k_prep_qk(int part, float scale,
                                                 __nv_bfloat16* __restrict__ oh,
                                                 __nv_bfloat16* __restrict__ ol) {
    size_t t = (size_t)blockIdx.x * 256 + threadIdx.x;
    int dg = (int)(t & 31);
    int s  = (int)((t >> 5) & 2047);
    int bh = (int)(t >> 16);
    int b = bh >> 4, h = bh & 15;
    float4 v = *reinterpret_cast<const float4*>(
        g_qkv + ((size_t)(b*2048 + s))*QKVCOLS + part*2048 + h*128 + dg*4);
    v.x *= scale; v.y *= scale; v.z *= scale; v.w *= scale;
    __nv_bfloat16 h0,h1,h2,h3,l0,l1,l2,l3;
    split_bf16(v.x,h0,l0); split_bf16(v.y,h1,l1);
    split_bf16(v.z,h2,l2); split_bf16(v.w,h3,l3);
    size_t o = (size_t)bh * HEADELEMS + (size_t)s*128 + dg*4;
    __nv_bfloat162* oh2 = reinterpret_cast<__nv_bfloat162*>(oh + o);
    __nv_bfloat162* ol2 = reinterpret_cast<__nv_bfloat162*>(ol + o);
    oh2[0] = __halves2bfloat162(h0,h1); oh2[1] = __halves2bfloat162(h2,h3);
    ol2[0] = __halves2bfloat162(l0,l1); ol2[1] = __halves2bfloat162(l2,l3);
}

__global__ __launch_bounds__(256) void k_prep_vt() {   // grid (4, 64, 32), block (32,8)
    __shared__ float t[32][33];
    int d0 = blockIdx.x * 32, s0 = blockIdx.y * 32, bh = blockIdx.z;
    int b = bh >> 4, h = bh & 15;
    int tx = threadIdx.x, ty = threadIdx.y;
#pragma unroll
    for (int i = 0; i < 32; i += 8)
        t[ty + i][tx] = g_qkv[(size_t)(b*2048 + s0 + ty + i)*QKVCOLS + 4096 + h*128 + d0 + tx];
    __syncthreads();
#pragma unroll
    for (int i = 0; i < 32; i += 8) {
        float a = t[tx][ty + i];   // V[s0+tx][d0+ty+i]
        __nv_bfloat16 hh, ll;
        split_bf16(a, hh, ll);
        size_t o = (size_t)bh * HEADELEMS + (size_t)(d0 + ty + i)*2048 + s0 + tx;
        g_vth[o] = hh;
        g_vtl[o] = ll;
    }
}

// ---------------------------------------------------------------------------
// bf16 GEMM via mma.sync (proven)
// ---------------------------------------------------------------------------
#define BKG   64
#define NKIT  (KP / BKG)
#define TILE_BYTES 16384
#define GEMM_SMEM  (1024 + 4 * TILE_BYTES)

__device__ __forceinline__ void load_tile_pair(uint32_t sA, uint32_t sB,
                                               const __nv_bfloat16* gA,
                                               const __nv_bfloat16* gB, int tid) {
#pragma unroll
    for (int t = 0; t < 4; ++t) {
        int i = tid + t * 256;
        int row = i >> 3, c = i & 7;
        uint32_t sw = (uint32_t)row * 128 + ((c * 16) ^ ((row & 7) * 16));
        cpa16(sA + sw, gA + (size_t)row * KP + c * 8);
        cpa16(sB + sw, gB + (size_t)row * KP + c * 8);
    }
}

template <bool BIAS>
__global__ __launch_bounds__(256) void k_gemm_mma(const __nv_bfloat16* __restrict__ A,
                                                  const __nv_bfloat16* __restrict__ B,
                                                  const float* __restrict__ bias,
                                                  float* __restrict__ C, int N) {
    extern __shared__ char smraw[];
    uint32_t sbase = (smem_to_u32(smraw) + 1023) & ~1023u;
    const int tid = threadIdx.x;
    const int m0 = blockIdx.y * 128, n0 = blockIdx.x * 128;
    const __nv_bfloat16* Ab = A + (size_t)m0 * KP;
    const __nv_bfloat16* Bb = B + (size_t)n0 * KP;

    load_tile_pair(sbase, sbase + TILE_BYTES, Ab, Bb, tid);
    CP_COMMIT();

    float c[4][4][4];
#pragma unroll
    for (int i = 0; i < 4; i++)
#pragma unroll
        for (int j = 0; j < 4; j++)
#pragma unroll
            for (int q = 0; q < 4; q++) c[i][j][q] = 0.f;

    const int wid = tid >> 5, lane = tid & 31;
    const int wm = wid & 1, wn = wid >> 1;
    const int a_row_base = wm * 64 + ((lane >> 3) & 1) * 8 + (lane & 7);
    const int a_byte     = (lane >> 4) * 16;
    const int b_row_off  = ((lane >> 4) & 1) * 8 + (lane & 7);
    const int b_byte     = ((lane >> 3) & 1) * 16;

    for (int kt = 0; kt < NKIT; ++kt) {
        uint32_t bufA = sbase + (kt & 1) * (2 * TILE_BYTES);
        uint32_t bufB = bufA + TILE_BYTES;
        if (kt + 1 < NKIT) {
            uint32_t nA = sbase + ((kt + 1) & 1) * (2 * TILE_BYTES);
            load_tile_pair(nA, nA + TILE_BYTES, Ab + (kt + 1) * BKG, Bb + (kt + 1) * BKG, tid);
        }
        CP_COMMIT();
        CP_WAIT1();
        __syncthreads();

#pragma unroll
        for (int s = 0; s < 4; ++s) {
            uint32_t a[4][4], b[2][4];
#pragma unroll
            for (int am = 0; am < 4; ++am) {
                int row = a_row_base + am * 16;
                uint32_t off = (uint32_t)row * 128 + ((s * 32 + a_byte) ^ ((row & 7) * 16));
                ldsm4(a[am][0], a[am][1], a[am][2], a[am][3], bufA + off);
            }
#pragma unroll
            for (int p = 0; p < 2; ++p) {
                int row = wn * 32 + p * 16 + b_row_off;
                uint32_t off = (uint32_t)row * 128 + ((s * 32 + b_byte) ^ ((row & 7) * 16));
                ldsm4(b[p][0], b[p][1], b[p][2], b[p][3], bufB + off);
            }
#pragma unroll
            for (int am = 0; am < 4; ++am)
#pragma unroll
                for (int an = 0; an < 4; ++an)
                    mma16816(c[am][an], a[am][0], a[am][1], a[am][2], a[am][3],
                             b[an >> 1][(an & 1) * 2], b[an >> 1][(an & 1) * 2 + 1]);
        }
        __syncthreads();
    }

    const int mrow = m0 + wm * 64;
    const int ncol = n0 + wn * 32;
#pragma unroll
    for (int am = 0; am < 4; ++am) {
        int r = mrow + am * 16 + (lane >> 2);
#pragma unroll
        for (int an = 0; an < 4; ++an) {
            int col = ncol + an * 8 + (lane & 3) * 2;
            float2 v0 = make_float2(c[am][an][0], c[am][an][1]);
            float2 v1 = make_float2(c[am][an][2], c[am][an][3]);
            if (BIAS) {
                float b0 = bias[col], b1 = bias[col + 1];
                v0.x += b0; v0.y += b1; v1.x += b0; v1.y += b1;
            }
            *reinterpret_cast<float2*>(C + (size_t)r * N + col)       = v0;
            *reinterpret_cast<float2*>(C + (size_t)(r + 8) * N + col) = v1;
        }
    }
}

// ---------------------------------------------------------------------------
// Tensor-core flash attention (bf16x3 compensated), causal.
// CTA: 128 queries x one (b,h); 8 warps x 16 rows. Key tiles of 64, dbl-buffered.
// smem map (from 1024-aligned base):
//   Q:  split*32768 + chunk*16384          (128 rows x 128B, chunk = d64 block)
//   K:  65536 + buf*32768 + split*16384 + chunk*8192   (64 rows x 128B)
//   Vt: 131072 + buf*32768 + split*16384   (128 d-rows x 128B of 64 keys)
// ---------------------------------------------------------------------------
#define ATT_SMEM (1024 + 196608)

__device__ __forceinline__ void load_rows(uint32_t sdst, const __nv_bfloat16* src,
                                          int srcStride, int nrows, int tid) {
    for (int i = tid; i < nrows * 8; i += 256) {
        int row = i >> 3, c = i & 7;
        uint32_t sw = (uint32_t)row * 128 + ((c * 16) ^ ((row & 7) * 16));
        cpa16(sdst + sw, src + (size_t)row * srcStride + c * 8);
    }
}

__global__ __launch_bounds__(256) void k_attn_tc() {
    extern __shared__ char smraw[];
    uint32_t sb = (smem_to_u32(smraw) + 1023) & ~1023u;
    const int tid = threadIdx.x, w = tid >> 5, lane = tid & 31;
    const int qblk = 15 - blockIdx.x;      // heavy blocks first
    const int bh   = blockIdx.y;
    const int q0   = qblk * 128;
    const size_t hb = (size_t)bh * HEADELEMS;

    const __nv_bfloat16* Qh  = g_qh  + hb + (size_t)q0 * 128;
    const __nv_bfloat16* Ql  = g_ql  + hb + (size_t)q0 * 128;
    const __nv_bfloat16* Kh  = g_kh  + hb;
    const __nv_bfloat16* Kl  = g_kl  + hb;
    const __nv_bfloat16* Vth = g_vth + hb;
    const __nv_bfloat16* Vtl = g_vtl + hb;

    // Q (both splits, both d-chunks)
    load_rows(sb + 0,     Qh,      128, 128, tid);
    load_rows(sb + 16384, Qh + 64, 128, 128, tid);
    load_rows(sb + 32768, Ql,      128, 128, tid);
    load_rows(sb + 49152, Ql + 64, 128, 128, tid);
    // KV tile 0 -> buf0
    {
        uint32_t kb = sb + 65536, vb = sb + 131072;
        load_rows(kb + 0,     Kh,      128, 64, tid);
        load_rows(kb + 8192,  Kh + 64, 128, 64, tid);
        load_rows(kb + 16384, Kl,      128, 64, tid);
        load_rows(kb + 24576, Kl + 64, 128, 64, tid);
        load_rows(vb + 0,     Vth,     2048, 128, tid);
        load_rows(vb + 16384, Vtl,     2048, 128, tid);
    }
    CP_COMMIT();

    const int ntiles = 2 * qblk + 2;

    float oc[16][4];
#pragma unroll
    for (int i = 0; i < 16; i++)
#pragma unroll
        for (int q = 0; q < 4; q++) oc[i][q] = 0.f;
    float m0 = -1e30f, m1 = -1e30f, l0 = 0.f, l1 = 0.f;

    const int a_row  = w * 16 + ((lane >> 3) & 1) * 8 + (lane & 7);
    const int a_byte = (lane >> 4) * 16;
    const int b_row  = ((lane >> 4) & 1) * 8 + (lane & 7);
    const int b_byte = ((lane >> 3) & 1) * 16;

    for (int j = 0; j < ntiles; ++j) {
        if (j + 1 < ntiles) {
            uint32_t kb = sb + 65536  + ((j + 1) & 1) * 32768;
            uint32_t vb = sb + 131072 + ((j + 1) & 1) * 32768;
            const __nv_bfloat16* kh = Kh + (size_t)(j + 1) * 64 * 128;
            const __nv_bfloat16* kl = Kl + (size_t)(j + 1) * 64 * 128;
            load_rows(kb + 0,     kh,      128, 64, tid);
            load_rows(kb + 8192,  kh + 64, 128, 64, tid);
            load_rows(kb + 16384, kl,      128, 64, tid);
            load_rows(kb + 24576, kl + 64, 128, 64, tid);
            load_rows(vb + 0,     Vth + (j + 1) * 64, 2048, 128, tid);
            load_rows(vb + 16384, Vtl + (j + 1) * 64, 2048, 128, tid);
        }
        CP_COMMIT();
        CP_WAIT1();
        __syncthreads();

        uint32_t kb = sb + 65536  + (j & 1) * 32768;
        uint32_t vb = sb + 131072 + (j & 1) * 32768;

        // ---- S = Q K^T (3-term) ----
        float sc[8][4];
#pragma unroll
        for (int t = 0; t < 8; t++)
#pragma unroll
            for (int q = 0; q < 4; q++) sc[t][q] = 0.f;

#pragma unroll
        for (int kst = 0; kst < 8; ++kst) {
            // FIXED (round 4 bug): 4 k16-steps per 64-d chunk, not 2.
            int ch = kst >> 2, sby = (kst & 3) * 32;
            uint32_t qoff = (uint32_t)a_row * 128 + ((sby + a_byte) ^ ((a_row & 7) * 16));
            uint32_t ah[4], al[4];
            ldsm4(ah[0], ah[1], ah[2], ah[3], sb + ch * 16384 + qoff);
            ldsm4(al[0], al[1], al[2], al[3], sb + 32768 + ch * 16384 + qoff);
            uint32_t bhf[4][4], blf[4][4];
#pragma unroll
            for (int p = 0; p < 4; ++p) {
                int row = p * 16 + b_row;
                uint32_t off = (uint32_t)row * 128 + ((sby + b_byte) ^ ((row & 7) * 16));
                ldsm4(bhf[p][0], bhf[p][1], bhf[p][2], bhf[p][3], kb + ch * 8192 + off);
                ldsm4(blf[p][0], blf[p][1], blf[p][2], blf[p][3], kb + 16384 + ch * 8192 + off);
            }
#pragma unroll
            for (int t = 0; t < 8; ++t) {
                int p = t >> 1, rr = (t & 1) * 2;
                mma16816(sc[t], ah[0], ah[1], ah[2], ah[3], bhf[p][rr], bhf[p][rr + 1]);
                mma16816(sc[t], ah[0], ah[1], ah[2], ah[3], blf[p][rr], blf[p][rr + 1]);
                mma16816(sc[t], al[0], al[1], al[2], al[3], bhf[p][rr], bhf[p][rr + 1]);
            }
        }

        // ---- causal mask (only partial tiles) ----
        if (j >= 2 * qblk) {
            int kbase = j * 64 + (lane & 3) * 2;
            int qrow  = q0 + w * 16 + (lane >> 2);
#pragma unroll
            for (int t = 0; t < 8; ++t) {
                int kc = kbase + t * 8;
                if (kc     > qrow)     sc[t][0] = -1e30f;
                if (kc + 1 > qrow)     sc[t][1] = -1e30f;
                if (kc     > qrow + 8) sc[t][2] = -1e30f;
                if (kc + 1 > qrow + 8) sc[t][3] = -1e30f;
            }
        }

        // ---- online softmax ----
        uint32_t pha0[8], pha1[8], pla0[8], pla1[8];
        float alpha0, alpha1;
        {
            float mx = -1e30f;
#pragma unroll
            for (int t = 0; t < 8; ++t) mx = fmaxf(mx, fmaxf(sc[t][0], sc[t][1]));
            mx = fmaxf(mx, __shfl_xor_sync(0xffffffffu, mx, 1));
            mx = fmaxf(mx, __shfl_xor_sync(0xffffffffu, mx, 2));
            float mn = fmaxf(m0, mx);
            alpha0 = __expf(m0 - mn); m0 = mn;
            float sum = 0.f;
#pragma unroll
            for (int t = 0; t < 8; ++t) {
                float p0 = __expf(sc[t][0] - mn), p1 = __expf(sc[t][1] - mn);
                sum += p0 + p1;
                split_pack(p0, p1, pha0[t], pla0[t]);
            }
            sum += __shfl_xor_sync(0xffffffffu, sum, 1);
            sum += __shfl_xor_sync(0xffffffffu, sum, 2);
            l0 = l0 * alpha0 + sum;
        }
        {
            float mx = -1e30f;
#pragma unroll
            for (int t = 0; t < 8; ++t) mx = fmaxf(mx, fmaxf(sc[t][2], sc[t][3]));
            mx = fmaxf(mx, __shfl_xor_sync(0xffffffffu, mx, 1));
            mx = fmaxf(mx, __shfl_xor_sync(0xffffffffu, mx, 2));
            float mn = fmaxf(m1, mx);
            alpha1 = __expf(m1 - mn); m1 = mn;
            float sum = 0.f;
#pragma unroll
            for (int t = 0; t < 8; ++t) {
                float p0 = __expf(sc[t][2] - mn), p1 = __expf(sc[t][3] - mn);
                sum += p0 + p1;
                split_pack(p0, p1, pha1[t], pla1[t]);
            }
            sum += __shfl_xor_sync(0xffffffffu, sum, 1);
            sum += __shfl_xor_sync(0xffffffffu, sum, 2);
            l1 = l1 * alpha1 + sum;
        }
        // rescale O
#pragma unroll
        for (int dt = 0; dt < 16; ++dt) {
            oc[dt][0] *= alpha0; oc[dt][1] *= alpha0;
            oc[dt][2] *= alpha1; oc[dt][3] *= alpha1;
        }

        // ---- O += P V (3-term) ----
#pragma unroll
        for (int kk = 0; kk < 4; ++kk) {
            uint32_t Ah0 = pha0[2*kk],   Ah1 = pha1[2*kk];
            uint32_t Ah2 = pha0[2*kk+1], Ah3 = pha1[2*kk+1];
            uint32_t Al0 = pla0[2*kk],   Al1 = pla1[2*kk];
            uint32_t Al2 = pla0[2*kk+1], Al3 = pla1[2*kk+1];
            uint32_t bhf[8][4], blf[8][4];
#pragma unroll
            for (int p = 0; p < 8; ++p) {
                int row = p * 16 + b_row;
                uint32_t off = (uint32_t)row * 128 + ((kk * 32 + b_byte) ^ ((row & 7) * 16));
                ldsm4(bhf[p][0], bhf[p][1], bhf[p][2], bhf[p][3], vb + off);
                ldsm4(blf[p][0], blf[p][1], blf[p][2], blf[p][3], vb + 16384 + off);
            }
#pragma unroll
            for (int dt = 0; dt < 16; ++dt) {
                int p = dt >> 1, rr = (dt & 1) * 2;
                mma16816(oc[dt], Ah0, Ah1, Ah2, Ah3, bhf[p][rr], bhf[p][rr + 1]);
                mma16816(oc[dt], Ah0, Ah1, Ah2, Ah3, blf[p][rr], blf[p][rr + 1]);
                mma16816(oc[dt], Al0, Al1, Al2, Al3, bhf[p][rr], bhf[p][rr + 1]);
            }
        }
        __syncthreads();
    }

    // ---- epilogue: O / l -> g_a3 packed bf16x3 ----
    float inv0 = 1.f / l0, inv1 = 1.f / l1;
    int b = bh >> 4, h = bh & 15;
    int r0 = q0 + w * 16 + (lane >> 2);
    size_t base0 = (size_t)(b * 2048 + r0) * KP + h * 128;
    size_t base1 = base0 + (size_t)8 * KP;
#pragma unroll
    for (int dt = 0; dt < 16; ++dt) {
        int d = dt * 8 + (lane & 3) * 2;
        uint32_t hi, lo;
        split_pack(oc[dt][0] * inv0, oc[dt][1] * inv0, hi, lo);
        *reinterpret_cast<uint32_t*>(g_a3 + base0 + d)        = hi;
        *reinterpret_cast<uint32_t*>(g_a3 + base0 + 2048 + d) = hi;
        *reinterpret_cast<uint32_t*>(g_a3 + base0 + 4096 + d) = lo;
        split_pack(oc[dt][2] * inv1, oc[dt][3] * inv1, hi, lo);
        *reinterpret_cast<uint32_t*>(g_a3 + base1 + d)        = hi;
        *reinterpret_cast<uint32_t*>(g_a3 + base1 + 2048 + d) = hi;
        *reinterpret_cast<uint32_t*>(g_a3 + base1 + 4096 + d) = lo;
    }
}

// ---------------------------------------------------------------------------
// Launch
// ---------------------------------------------------------------------------
extern "C" void kernel_launch(void* const* d_in, const int* in_sizes, int n_in,
                              void* d_out, int out_size) {
    const float* x     = (const float*)d_in[0];
    const float* Wqkv  = (const float*)d_in[1];
    const float* Wproj = (const float*)d_in[2];
    const float* bproj = (const float*)d_in[3];
    float* out = (float*)d_out;
    (void)in_sizes; (void)n_in; (void)out_size;

    cudaFuncSetAttribute(k_gemm_mma<false>, cudaFuncAttributeMaxDynamicSharedMemorySize, GEMM_SMEM);
    cudaFuncSetAttribute(k_gemm_mma<true>,  cudaFuncAttributeMaxDynamicSharedMemorySize, GEMM_SMEM);
    cudaFuncSetAttribute(k_attn_tc,         cudaFuncAttributeMaxDynamicSharedMemorySize, ATT_SMEM);

    __nv_bfloat16 *x3, *wq3, *wp3, *a3, *qh, *ql, *kh, *kl;
    float* qkv;
    cudaGetSymbolAddress((void**)&x3,  g_x3);
    cudaGetSymbolAddress((void**)&wq3, g_wqkv3);
    cudaGetSymbolAddress((void**)&wp3, g_wp3);
    cudaGetSymbolAddress((void**)&a3,  g_a3);
    cudaGetSymbolAddress((void**)&qkv, g_qkv);
    cudaGetSymbolAddress((void**)&qh,  g_qh);
    cudaGetSymbolAddress((void**)&ql,  g_ql);
    cudaGetSymbolAddress((void**)&kh,  g_kh);
    cudaGetSymbolAddress((void**)&kl,  g_kl);

    // 1) Pack inputs for GEMM1
    k_split_pack<<<(ROWS * 2048 / 4) / 256, 256>>>(x, x3);
    k_tsplit_pack<<<dim3(QKVCOLS / 32, 2048 / 32), dim3(32, 8)>>>(Wqkv, wq3, QKVCOLS);
    k_tsplit_pack<<<dim3(DOUT / 32, 2048 / 32), dim3(32, 8)>>>(Wproj, wp3, DOUT);

    // 2) GEMM1: qkv = x @ Wqkv (fp32)
    k_gemm_mma<false><<<dim3(QKVCOLS / 128, ROWS / 128), 256, GEMM_SMEM>>>(
        x3, wq3, nullptr, qkv, QKVCOLS);

    // 3) Attention pre-passes (split + layout)
    const float scale = 0.08838834764831845f;   // 1/sqrt(128)
    k_prep_qk<<<8192, 256>>>(0, scale, qh, ql);
    k_prep_qk<<<8192, 256>>>(1, 1.0f,  kh, kl);
    k_prep_vt<<<dim3(4, 64, 32), dim3(32, 8)>>>();

    // 4) Tensor-core attention -> g_a3 (packed bf16x3)
    k_attn_tc<<<dim3(16, 32), 256, ATT_SMEM>>>();

    // 5) GEMM2: out = attn @ Wproj + bias
    k_gemm_mma<true><<<dim3(DOUT / 128, ROWS / 128), 256, GEMM_SMEM>>>(
        a3, wp3, bproj, out, DOUT);
}